// round 3
// baseline (speedup 1.0000x reference)
#include <cuda_runtime.h>
#include <cuda_bf16.h>
#include <mma.h>

using namespace nvcuda;

#define BATCH 8
#define HW    4096
#define CH    512
#define NTOK  (BATCH * HW)   // 32768

// ---------------- scratch (device globals; no allocation APIs) ----------------
__device__ float         g_psum  [64 * BATCH * CH];
__device__ float         g_psumsq[64 * BATCH * CH];
__device__ float         g_mean  [BATCH * CH];
__device__ float         g_rstd  [BATCH * CH];
__device__ float         g_xn [(size_t)NTOK * CH];          // 64 MB
__device__ __nv_bfloat16 g_xnb[(size_t)NTOK * CH];          // 32 MB
__device__ __nv_bfloat16 g_wq[CH * CH], g_wk[CH * CH], g_wv[CH * CH], g_wp[CH * CH];
__device__ __nv_bfloat16 g_q [(size_t)NTOK * CH];
__device__ __nv_bfloat16 g_k [(size_t)NTOK * CH];
__device__ __nv_bfloat16 g_v [(size_t)NTOK * CH];
__device__ __nv_bfloat16 g_ao[(size_t)NTOK * CH];
__device__ float         g_tmp[(size_t)NTOK * CH];          // 64 MB
__device__ float         g_S[(size_t)BATCH * HW * HW];      // 512 MB
__device__ __nv_bfloat16 g_P[(size_t)BATCH * HW * HW];      // 256 MB

// ---------------- helpers ----------------
static __device__ __forceinline__ void st4bf(__nv_bfloat16* p, float a, float b, float c, float d) {
    __nv_bfloat162* q2 = (__nv_bfloat162*)p;
    q2[0] = __floats2bfloat162_rn(a, b);
    q2[1] = __floats2bfloat162_rn(c, d);
}

// ---------------- weight convert: f32 -> bf16 (4 weights at once) ----------------
__global__ void wconv_kernel(const float* __restrict__ wq, const float* __restrict__ wk,
                             const float* __restrict__ wv, const float* __restrict__ wp) {
    int i = blockIdx.x * blockDim.x + threadIdx.x;   // 0..65535 (CH*CH/4)
    if (i >= CH * CH / 4) return;
    float4 a = ((const float4*)wq)[i];
    st4bf(g_wq + 4 * i, a.x, a.y, a.z, a.w);
    float4 b = ((const float4*)wk)[i];
    st4bf(g_wk + 4 * i, b.x, b.y, b.z, b.w);
    float4 c = ((const float4*)wv)[i];
    st4bf(g_wv + 4 * i, c.x, c.y, c.z, c.w);
    float4 d = ((const float4*)wp)[i];
    st4bf(g_wp + 4 * i, d.x, d.y, d.z, d.w);
}

// ---------------- groupnorm (instance norm) stats: partials then finalize ----------------
__global__ void gn_partial_kernel(const float* __restrict__ x) {
    int b  = blockIdx.z;            // 0..7
    int ct = blockIdx.y;            // 0..3
    int st = blockIdx.x;            // 0..63
    int c  = ct * 128 + threadIdx.x;
    size_t base = ((size_t)b * HW + (size_t)st * 64) * CH + c;
    float s = 0.f, ss = 0.f;
#pragma unroll 8
    for (int r = 0; r < 64; r++) {
        float f = x[base + (size_t)r * CH];
        s += f; ss += f * f;
    }
    int idx = b * CH + c;
    g_psum  [st * (BATCH * CH) + idx] = s;
    g_psumsq[st * (BATCH * CH) + idx] = ss;
}

__global__ void gn_final_kernel() {
    int idx = blockIdx.x * blockDim.x + threadIdx.x;   // 0..4095 (= b*CH + c)
    if (idx >= BATCH * CH) return;
    float s = 0.f, ss = 0.f;
#pragma unroll 8
    for (int st = 0; st < 64; st++) {
        s  += g_psum  [st * (BATCH * CH) + idx];
        ss += g_psumsq[st * (BATCH * CH) + idx];
    }
    float mean = s * (1.0f / HW);
    float var  = ss * (1.0f / HW) - mean * mean;
    g_mean[idx] = mean;
    g_rstd[idx] = rsqrtf(var + 1e-3f);
}

__global__ void gn_apply_kernel(const float* __restrict__ x,
                                const float* __restrict__ gamma,
                                const float* __restrict__ beta) {
    size_t i = ((size_t)blockIdx.x * blockDim.x + threadIdx.x) * 4;
    int c0 = (int)(i & (CH - 1));
    int n  = (int)(i >> 9);
    int b  = n >> 12;
    int bc = b * CH + c0;
    float4 xv = *(const float4*)(x + i);
    float4 r;
    r.x = (xv.x - g_mean[bc + 0]) * g_rstd[bc + 0] * gamma[c0 + 0] + beta[c0 + 0];
    r.y = (xv.y - g_mean[bc + 1]) * g_rstd[bc + 1] * gamma[c0 + 1] + beta[c0 + 1];
    r.z = (xv.z - g_mean[bc + 2]) * g_rstd[bc + 2] * gamma[c0 + 2] + beta[c0 + 2];
    r.w = (xv.w - g_mean[bc + 3]) * g_rstd[bc + 3] * gamma[c0 + 3] + beta[c0 + 3];
    *(float4*)(g_xn + i) = r;
    st4bf(g_xnb + i, r.x, r.y, r.z, r.w);
}

// ---------------- bf16 wmma GEMM: C(f32) = A(bf16,[M,K]) * B ----------------
// BT=false: B is row-major [K,N] with row stride ldb.
// BT=true : B is row-major [N,K] with row stride ldb (i.e. C = A * B^T).
template <bool BT>
__global__ __launch_bounds__(256) void gemm_bf16_kernel(
    const __nv_bfloat16* __restrict__ A,
    const __nv_bfloat16* __restrict__ B,
    float* __restrict__ C,
    int M, int N, int K, int lda, int ldb, int ldc,
    long long strideA, long long strideB, long long strideC)
{
    constexpr int BM = 128, BN = 128, BK = 32, PAD = 8;
    A += (long long)blockIdx.z * strideA;
    B += (long long)blockIdx.z * strideB;
    C += (long long)blockIdx.z * strideC;

    const int mBase = blockIdx.y * BM;
    const int nBase = blockIdx.x * BN;

    __shared__ __nv_bfloat16 shA[2][BM][BK + PAD];
    constexpr int SBR = BT ? BN : BK;
    constexpr int SBC = BT ? (BK + PAD) : (BN + PAD);
    __shared__ __nv_bfloat16 shB[2][SBR][SBC];

    const int tid = threadIdx.x;
    const int wid = tid >> 5;
    const int wm = wid & 3;        // 4 warp rows
    const int wn = wid >> 2;       // 2 warp cols
    const int m0 = wm * 32;
    const int n0 = wn * 64;

    wmma::fragment<wmma::accumulator, 16, 16, 16, float> cf[2][4];
#pragma unroll
    for (int i = 0; i < 2; i++)
#pragma unroll
        for (int j = 0; j < 4; j++) wmma::fill_fragment(cf[i][j], 0.0f);

    uint4 ra[2], rb[2];

    auto fetchA = [&](int t) {
        int kb = t * BK;
#pragma unroll
        for (int i = 0; i < 2; i++) {
            int id = tid + i * 256;
            int r = id >> 2, cc = (id & 3) * 8;
            ra[i] = *(const uint4*)(A + (size_t)(mBase + r) * lda + kb + cc);
        }
    };
    auto storeA = [&](int buf) {
#pragma unroll
        for (int i = 0; i < 2; i++) {
            int id = tid + i * 256;
            int r = id >> 2, cc = (id & 3) * 8;
            *(uint4*)&shA[buf][r][cc] = ra[i];
        }
    };
    auto fetchB = [&](int t) {
        int kb = t * BK;
#pragma unroll
        for (int i = 0; i < 2; i++) {
            int id = tid + i * 256;
            if (BT) {
                int r = id >> 2, cc = (id & 3) * 8;
                rb[i] = *(const uint4*)(B + (size_t)(nBase + r) * ldb + kb + cc);
            } else {
                int r = id >> 4, cc = (id & 15) * 8;
                rb[i] = *(const uint4*)(B + (size_t)(kb + r) * ldb + nBase + cc);
            }
        }
    };
    auto storeB = [&](int buf) {
#pragma unroll
        for (int i = 0; i < 2; i++) {
            int id = tid + i * 256;
            if (BT) {
                int r = id >> 2, cc = (id & 3) * 8;
                *(uint4*)&shB[buf][r][cc] = rb[i];
            } else {
                int r = id >> 4, cc = (id & 15) * 8;
                *(uint4*)&shB[buf][r][cc] = rb[i];
            }
        }
    };
    auto compute = [&](int buf) {
#pragma unroll
        for (int ks = 0; ks < BK; ks += 16) {
            wmma::fragment<wmma::matrix_a, 16, 16, 16, __nv_bfloat16, wmma::row_major> af[2];
#pragma unroll
            for (int i = 0; i < 2; i++)
                wmma::load_matrix_sync(af[i], &shA[buf][m0 + i * 16][ks], BK + PAD);
            if constexpr (BT) {
#pragma unroll
                for (int j = 0; j < 4; j++) {
                    wmma::fragment<wmma::matrix_b, 16, 16, 16, __nv_bfloat16, wmma::col_major> bf;
                    wmma::load_matrix_sync(bf, &shB[buf][n0 + j * 16][ks], BK + PAD);
#pragma unroll
                    for (int i = 0; i < 2; i++) wmma::mma_sync(cf[i][j], af[i], bf, cf[i][j]);
                }
            } else {
#pragma unroll
                for (int j = 0; j < 4; j++) {
                    wmma::fragment<wmma::matrix_b, 16, 16, 16, __nv_bfloat16, wmma::row_major> bf;
                    wmma::load_matrix_sync(bf, &shB[buf][ks][n0 + j * 16], BN + PAD);
#pragma unroll
                    for (int i = 0; i < 2; i++) wmma::mma_sync(cf[i][j], af[i], bf, cf[i][j]);
                }
            }
        }
    };

    const int nk = K / BK;
    fetchA(0); fetchB(0);
    storeA(0); storeB(0);
    __syncthreads();
    for (int t = 0; t < nk; t++) {
        int cur = t & 1;
        if (t + 1 < nk) { fetchA(t + 1); fetchB(t + 1); }
        compute(cur);
        if (t + 1 < nk) {
            storeA(cur ^ 1); storeB(cur ^ 1);
            __syncthreads();
        }
    }

#pragma unroll
    for (int i = 0; i < 2; i++)
#pragma unroll
        for (int j = 0; j < 4; j++) {
            float* cp = C + (size_t)(mBase + m0 + i * 16) * ldc + (nBase + n0 + j * 16);
            wmma::store_matrix_sync(cp, cf[i][j], ldc, wmma::mem_row_major);
        }
}

// ---------------- softmax per row (4096 cols), f32 in -> bf16 out ----------------
__global__ __launch_bounds__(256) void softmax_kernel(const float* __restrict__ S,
                                                      __nv_bfloat16* __restrict__ P) {
    size_t row = blockIdx.x;
    const float* s = S + row * (size_t)HW;
    __nv_bfloat16* p = P + row * (size_t)HW;
    int tid = threadIdx.x;
    int lane = tid & 31, wid = tid >> 5;
    __shared__ float red[8];

    float v[16];
#pragma unroll
    for (int t = 0; t < 16; t++) v[t] = s[tid + t * 256];

    float m = v[0];
#pragma unroll
    for (int t = 1; t < 16; t++) m = fmaxf(m, v[t]);
#pragma unroll
    for (int o = 16; o >= 1; o >>= 1) m = fmaxf(m, __shfl_xor_sync(0xffffffffu, m, o));
    if (lane == 0) red[wid] = m;
    __syncthreads();
    float bm = red[0];
#pragma unroll
    for (int w = 1; w < 8; w++) bm = fmaxf(bm, red[w]);
    __syncthreads();

    float sum = 0.f;
#pragma unroll
    for (int t = 0; t < 16; t++) { v[t] = __expf(v[t] - bm); sum += v[t]; }
#pragma unroll
    for (int o = 16; o >= 1; o >>= 1) sum += __shfl_xor_sync(0xffffffffu, sum, o);
    if (lane == 0) red[wid] = sum;
    __syncthreads();
    float bs = 0.f;
#pragma unroll
    for (int w = 0; w < 8; w++) bs += red[w];
    float inv = 1.0f / bs;
#pragma unroll
    for (int t = 0; t < 16; t += 2)
        st4bf(p + tid * 0 + 0, 0.f, 0.f, 0.f, 0.f);  // (dead store pattern avoided below)
    // strided scalar stores (bf16), same addressing as loads
#pragma unroll
    for (int t = 0; t < 16; t++) p[tid + t * 256] = __float2bfloat16(v[t] * inv);
}

// ---------------- post kernels ----------------
__global__ void qkv_post_kernel(const float* __restrict__ t, const float* __restrict__ bias,
                                __nv_bfloat16* __restrict__ out, float alpha) {
    size_t i = ((size_t)blockIdx.x * blockDim.x + threadIdx.x) * 4;
    int c0 = (int)(i & (CH - 1));
    float4 v = *(const float4*)(t + i);
    st4bf(out + i, (v.x + bias[c0 + 0]) * alpha, (v.y + bias[c0 + 1]) * alpha,
                   (v.z + bias[c0 + 2]) * alpha, (v.w + bias[c0 + 3]) * alpha);
}

__global__ void bf16_post_kernel(const float* __restrict__ t, __nv_bfloat16* __restrict__ out) {
    size_t i = ((size_t)blockIdx.x * blockDim.x + threadIdx.x) * 4;
    float4 v = *(const float4*)(t + i);
    st4bf(out + i, v.x, v.y, v.z, v.w);
}

__global__ void final_post_kernel(const float* __restrict__ t, const float* __restrict__ bp,
                                  float* __restrict__ out) {
    size_t i = ((size_t)blockIdx.x * blockDim.x + threadIdx.x) * 4;
    int c0 = (int)(i & (CH - 1));
    float4 v = *(const float4*)(t + i);
    float4 xn = *(const float4*)(g_xn + i);
    float4 r;
    r.x = v.x + bp[c0 + 0] + xn.x;
    r.y = v.y + bp[c0 + 1] + xn.y;
    r.z = v.z + bp[c0 + 2] + xn.z;
    r.w = v.w + bp[c0 + 3] + xn.w;
    *(float4*)(out + i) = r;
}

// ---------------- launch ----------------
extern "C" void kernel_launch(void* const* d_in, const int* in_sizes, int n_in,
                              void* d_out, int out_size) {
    (void)in_sizes; (void)n_in; (void)out_size;
    const float* x     = (const float*)d_in[0];
    const float* gamma = (const float*)d_in[1];
    const float* beta  = (const float*)d_in[2];
    const float* Wq    = (const float*)d_in[3];
    const float* bq    = (const float*)d_in[4];
    const float* Wk    = (const float*)d_in[5];
    const float* bk    = (const float*)d_in[6];
    const float* Wv    = (const float*)d_in[7];
    const float* bv    = (const float*)d_in[8];
    const float* Wp    = (const float*)d_in[9];
    const float* bp    = (const float*)d_in[10];
    float* out = (float*)d_out;

    // device symbol addresses
    float *p_tmp, *p_S;
    __nv_bfloat16 *p_xnb, *p_wq, *p_wk, *p_wv, *p_wp, *p_q, *p_k, *p_v, *p_ao, *p_P;
    cudaGetSymbolAddress((void**)&p_tmp, g_tmp);
    cudaGetSymbolAddress((void**)&p_S,   g_S);
    cudaGetSymbolAddress((void**)&p_xnb, g_xnb);
    cudaGetSymbolAddress((void**)&p_wq,  g_wq);
    cudaGetSymbolAddress((void**)&p_wk,  g_wk);
    cudaGetSymbolAddress((void**)&p_wv,  g_wv);
    cudaGetSymbolAddress((void**)&p_wp,  g_wp);
    cudaGetSymbolAddress((void**)&p_q,   g_q);
    cudaGetSymbolAddress((void**)&p_k,   g_k);
    cudaGetSymbolAddress((void**)&p_v,   g_v);
    cudaGetSymbolAddress((void**)&p_ao,  g_ao);
    cudaGetSymbolAddress((void**)&p_P,   g_P);

    const int elemBlocks = (NTOK * CH / 4) / 256;   // 16384
    const float scale = 1.0f / sqrtf((float)CH);

    wconv_kernel<<<(CH * CH / 4 + 255) / 256, 256>>>(Wq, Wk, Wv, Wp);
    gn_partial_kernel<<<dim3(64, 4, BATCH), 128>>>(x);
    gn_final_kernel<<<(BATCH * CH + 255) / 256, 256>>>();
    gn_apply_kernel<<<elemBlocks, 256>>>(x, gamma, beta);

    // Q = xn @ Wq (+bq, *scale)  ;  K = xn @ Wk (+bk)  ;  V = xn @ Wv (+bv)
    gemm_bf16_kernel<false><<<dim3(CH / 128, NTOK / 128, 1), 256>>>(
        p_xnb, p_wq, p_tmp, NTOK, CH, CH, CH, CH, CH, 0, 0, 0);
    qkv_post_kernel<<<elemBlocks, 256>>>(p_tmp, bq, p_q, scale);
    gemm_bf16_kernel<false><<<dim3(CH / 128, NTOK / 128, 1), 256>>>(
        p_xnb, p_wk, p_tmp, NTOK, CH, CH, CH, CH, CH, 0, 0, 0);
    qkv_post_kernel<<<elemBlocks, 256>>>(p_tmp, bk, p_k, 1.0f);
    gemm_bf16_kernel<false><<<dim3(CH / 128, NTOK / 128, 1), 256>>>(
        p_xnb, p_wv, p_tmp, NTOK, CH, CH, CH, CH, CH, 0, 0, 0);
    qkv_post_kernel<<<elemBlocks, 256>>>(p_tmp, bv, p_v, 1.0f);

    // S = Q @ K^T  (batched over B)
    gemm_bf16_kernel<true><<<dim3(HW / 128, HW / 128, BATCH), 256>>>(
        p_q, p_k, p_S, HW, HW, CH, CH, CH, HW,
        (long long)HW * CH, (long long)HW * CH, (long long)HW * HW);

    // P = softmax(S) rows
    softmax_kernel<<<NTOK, 256>>>(p_S, p_P);

    // AO = P @ V (batched)
    gemm_bf16_kernel<false><<<dim3(CH / 128, HW / 128, BATCH), 256>>>(
        p_P, p_v, p_tmp, HW, CH, HW, HW, CH, CH,
        (long long)HW * HW, (long long)HW * CH, (long long)HW * CH);
    bf16_post_kernel<<<elemBlocks, 256>>>(p_tmp, p_ao);

    // OUT = AO @ Wp + bp + xn
    gemm_bf16_kernel<false><<<dim3(CH / 128, NTOK / 128, 1), 256>>>(
        p_ao, p_wp, p_tmp, NTOK, CH, CH, CH, CH, CH, 0, 0, 0);
    final_post_kernel<<<elemBlocks, 256>>>(p_tmp, bp, out);
}